// round 6
// baseline (speedup 1.0000x reference)
#include <cuda_runtime.h>

#define BB 128  // batch
#define BV 32   // batch in float4 units (logic layers)
#define BH 64   // batch in float2 units (conv layers)

typedef unsigned long long ull;

// ---------------- padded geometry (halos stay zero: never written) ---------
__device__ __align__(16) float g_bin[9 * 34 * 34 * BB];
__device__ __align__(16) float g_h1[32 * 18 * 18 * BB];
__device__ __align__(16) float g_h2[128 * 10 * 10 * BB];
__device__ __align__(16) float g_h3[512 * 6 * 6 * BB];
__device__ __align__(16) float g_h4[4096 * BB];
__device__ __align__(16) float g_g1[40960 * BB];
__device__ __align__(16) float g_g2[20480 * BB];
__device__ __align__(16) float g_mix[83552 * 4];
__device__ __align__(16) float g_part[160 * BB];

__constant__ float GC[64] = {
    0, 0, 0, 0,   0, 0, 0, 1,   0, 1, 0, -1,  0, 1, 0, 0,
    0, 0, 1, -1,  0, 0, 1, 0,   0, 1, 1, -2,  0, 1, 1, -1,
    1, -1, -1, 1, 1, -1, -1, 2, 1, 0, -1, 0,  1, 0, -1, 1,
    1, -1, 0, 0,  1, -1, 0, 1,  1, 0, 0, -1,  1, 0, 0, 0};

#define OFF_C1 0
#define OFF_C2 224
#define OFF_C3 1120
#define OFF_C4 4704
#define OFF_L1 11872
#define OFF_L2 52832
#define OFF_L3 73312
#define N_NODES 83552

// ---------------- packed f32x2 helpers ----------------
__device__ __forceinline__ ull pk2(float v) {
    ull r; unsigned int u = __float_as_uint(v);
    asm("mov.b64 %0, {%1, %1};" : "=l"(r) : "r"(u));
    return r;
}
__device__ __forceinline__ void unpk2(ull v, float& lo, float& hi) {
    unsigned int a, b;
    asm("mov.b64 {%0, %1}, %2;" : "=r"(a), "=r"(b) : "l"(v));
    lo = __uint_as_float(a); hi = __uint_as_float(b);
}
// w0 + w1*a + w2*b + w3*(a*b), two fp32 lanes per instruction
__device__ __forceinline__ ull gate2p(ull a, ull b, ull w0, ull w1, ull w2, ull w3) {
    ull ab, r;
    asm("mul.rn.f32x2 %0, %1, %2;" : "=l"(ab) : "l"(a), "l"(b));
    asm("fma.rn.f32x2 %0, %1, %2, %3;" : "=l"(r) : "l"(a), "l"(w1), "l"(w0));
    asm("fma.rn.f32x2 %0, %1, %2, %3;" : "=l"(r) : "l"(b), "l"(w2), "l"(r));
    asm("fma.rn.f32x2 %0, %1, %2, %3;" : "=l"(r) : "l"(ab), "l"(w3), "l"(r));
    return r;
}

__device__ __forceinline__ float4 f4(float v) { return make_float4(v, v, v, v); }
__device__ __forceinline__ float4 gate4v(float4 a, float4 b, float w0, float w1, float w2, float w3) {
    float4 r;
    r.x = fmaf(w3, a.x * b.x, fmaf(w2, b.x, fmaf(w1, a.x, w0)));
    r.y = fmaf(w3, a.y * b.y, fmaf(w2, b.y, fmaf(w1, a.y, w0)));
    r.z = fmaf(w3, a.z * b.z, fmaf(w2, b.z, fmaf(w1, a.z, w0)));
    r.w = fmaf(w3, a.w * b.w, fmaf(w2, b.w, fmaf(w1, a.w, w0)));
    return r;
}

// ---------------- kernel 1: gate mixing ----------------
__global__ void mix_kernel(const float* __restrict__ s0, const float* __restrict__ s1,
                           const float* __restrict__ s2, const float* __restrict__ s3,
                           const float* __restrict__ s4, const float* __restrict__ s5,
                           const float* __restrict__ s6, float* __restrict__ dst) {
    int tid = blockIdx.x * blockDim.x + threadIdx.x;
    if (tid >= N_NODES) return;
    const int offs[8] = {OFF_C1, OFF_C2, OFF_C3, OFF_C4, OFF_L1, OFF_L2, OFF_L3, N_NODES};
    const float* srcs[7] = {s0, s1, s2, s3, s4, s5, s6};
    int seg = 0;
    while (tid >= offs[seg + 1]) seg++;
    const float* w = srcs[seg] + (size_t)(tid - offs[seg]) * 16;

    float e[16];
    float mx = w[0];
#pragma unroll
    for (int i = 1; i < 16; i++) mx = fmaxf(mx, w[i]);
    float s = 0.f;
#pragma unroll
    for (int i = 0; i < 16; i++) { e[i] = __expf(w[i] - mx); s += e[i]; }
    float inv = 1.f / s;
    float m0 = 0.f, m1 = 0.f, m2 = 0.f, m3 = 0.f;
#pragma unroll
    for (int i = 0; i < 16; i++) {
        float p = e[i] * inv;
        m0 = fmaf(p, GC[i * 4 + 0], m0);
        m1 = fmaf(p, GC[i * 4 + 1], m1);
        m2 = fmaf(p, GC[i * 4 + 2], m2);
        m3 = fmaf(p, GC[i * 4 + 3], m3);
    }
    float4 o; o.x = m0; o.y = m1; o.z = m2; o.w = m3;
    ((float4*)dst)[tid] = o;
}

// ---------------- kernel 2: binarize + BCHW -> CHWB (padded out) -----------
__global__ void binarize_kernel(const float* __restrict__ x, float* __restrict__ bin) {
    __shared__ float tile[32][33];
    int c = blockIdx.z;
    int h = blockIdx.y;
    int bc = blockIdx.x;
    int b = bc * 32 + threadIdx.y;
    tile[threadIdx.y][threadIdx.x] = x[(((size_t)b * 3 + c) * 32 + h) * 32 + threadIdx.x];
    __syncthreads();
    int w = threadIdx.y;
    int bout = bc * 32 + threadIdx.x;
    float v = tile[threadIdx.x][w];
    const float thr[3] = {0.25f, 0.5f, 0.75f};
#pragma unroll
    for (int t = 0; t < 3; t++) {
        size_t idx = (((size_t)(t * 3 + c)) * 34 * 34 + (size_t)(h + 1) * 34 + (w + 1)) * BB + bout;
        bin[idx] = (v > thr[t]) ? 1.f : 0.f;
    }
}

// ---------------- tree_conv + or_pool: packed f32x2, imm-offset loads ------
template <int Hin, int SPB, bool PADOUT>
__global__ void __launch_bounds__(64 * SPB, 2) tree_conv_kernel(
    const float* __restrict__ in, float2* __restrict__ out,
    const int* __restrict__ leaf, const float* __restrict__ mix) {
    constexpr int Win = Hin + 2;
    constexpr int Wo = Hin / 2;
    constexpr int Wop = PADOUT ? (Wo + 2) : Wo;
    // pixel offsets within padded plane, in float2 units (compile-time)
    constexpr int QOFF0 = 0;
    constexpr int QOFF1 = BH;
    constexpr int QOFF2 = Win * BH;
    constexpr int QOFF3 = Win * BH + BH;

    int o = blockIdx.y;
    __shared__ ull smw[28];   // packed (duplicated) gate coefs
    __shared__ int soff[8];   // per-leaf base offset (float2 units)
    int t = threadIdx.y * 64 + threadIdx.x;
    if (t < 28) smw[t] = pk2(mix[o * 28 + t]);
    if (t < 8) {
        int idx = leaf[o * 8 + t];
        int ch = idx / 9, p = idx % 9;
        int dy = p / 3, dx = p % 3;
        soff[t] = (ch * Win * Win + dy * Win + dx) * BH;
    }
    __syncthreads();

    int s = blockIdx.x * SPB + threadIdx.y;
    int wo = s % Wo, ho = s / Wo;
    int lane = threadIdx.x;
    int posbase = (2 * ho * Win + 2 * wo) * BH + lane;

    // 8 per-leaf base pointers (imm-offset loads from these)
    const ull* base[8];
#pragma unroll
    for (int l = 0; l < 8; l++) base[l] = (const ull*)in + soff[l] + posbase;

    // coefs into registers
    ull w[28];
#pragma unroll
    for (int k = 0; k < 28; k++) w[k] = smw[k];

    ull v0[8], v1[8], z[4];
#pragma unroll
    for (int l = 0; l < 8; l++) v0[l] = base[l][QOFF0];   // prefetch q0

    // q0 : prefetch q1
#pragma unroll
    for (int l = 0; l < 8; l++) v1[l] = base[l][QOFF1];
    {
        ull t0 = gate2p(v0[0], v0[1], w[0], w[1], w[2], w[3]);
        ull t1 = gate2p(v0[2], v0[3], w[4], w[5], w[6], w[7]);
        ull t2 = gate2p(v0[4], v0[5], w[8], w[9], w[10], w[11]);
        ull t3 = gate2p(v0[6], v0[7], w[12], w[13], w[14], w[15]);
        ull u0 = gate2p(t0, t1, w[16], w[17], w[18], w[19]);
        ull u1 = gate2p(t2, t3, w[20], w[21], w[22], w[23]);
        z[0] = gate2p(u0, u1, w[24], w[25], w[26], w[27]);
    }
    // q1 : prefetch q2
#pragma unroll
    for (int l = 0; l < 8; l++) v0[l] = base[l][QOFF2];
    {
        ull t0 = gate2p(v1[0], v1[1], w[0], w[1], w[2], w[3]);
        ull t1 = gate2p(v1[2], v1[3], w[4], w[5], w[6], w[7]);
        ull t2 = gate2p(v1[4], v1[5], w[8], w[9], w[10], w[11]);
        ull t3 = gate2p(v1[6], v1[7], w[12], w[13], w[14], w[15]);
        ull u0 = gate2p(t0, t1, w[16], w[17], w[18], w[19]);
        ull u1 = gate2p(t2, t3, w[20], w[21], w[22], w[23]);
        z[1] = gate2p(u0, u1, w[24], w[25], w[26], w[27]);
    }
    // q2 : prefetch q3
#pragma unroll
    for (int l = 0; l < 8; l++) v1[l] = base[l][QOFF3];
    {
        ull t0 = gate2p(v0[0], v0[1], w[0], w[1], w[2], w[3]);
        ull t1 = gate2p(v0[2], v0[3], w[4], w[5], w[6], w[7]);
        ull t2 = gate2p(v0[4], v0[5], w[8], w[9], w[10], w[11]);
        ull t3 = gate2p(v0[6], v0[7], w[12], w[13], w[14], w[15]);
        ull u0 = gate2p(t0, t1, w[16], w[17], w[18], w[19]);
        ull u1 = gate2p(t2, t3, w[20], w[21], w[22], w[23]);
        z[2] = gate2p(u0, u1, w[24], w[25], w[26], w[27]);
    }
    // q3
    {
        ull t0 = gate2p(v1[0], v1[1], w[0], w[1], w[2], w[3]);
        ull t1 = gate2p(v1[2], v1[3], w[4], w[5], w[6], w[7]);
        ull t2 = gate2p(v1[4], v1[5], w[8], w[9], w[10], w[11]);
        ull t3 = gate2p(v1[6], v1[7], w[12], w[13], w[14], w[15]);
        ull u0 = gate2p(t0, t1, w[16], w[17], w[18], w[19]);
        ull u1 = gate2p(t2, t3, w[20], w[21], w[22], w[23]);
        z[3] = gate2p(u0, u1, w[24], w[25], w[26], w[27]);
    }

    float l0, h0, l1h, h1h, l2, h2, l3, h3;
    unpk2(z[0], l0, h0); unpk2(z[1], l1h, h1h); unpk2(z[2], l2, h2); unpk2(z[3], l3, h3);
    float rlo = fmaxf(fmaxf(l0, l1h), fmaxf(l2, l3));
    float rhi = fmaxf(fmaxf(h0, h1h), fmaxf(h2, h3));

    size_t oidx;
    if (PADOUT)
        oidx = ((size_t)o * Wop * Wop + (size_t)(ho + 1) * Wop + (wo + 1)) * BH + lane;
    else
        oidx = ((size_t)o * Wo * Wo + (size_t)ho * Wo + wo) * BH + lane;
    out[oidx] = make_float2(rlo, rhi);
}

// ---------------- logic layers (float4 lanes) ----------------
__global__ void logic_kernel(const float4* __restrict__ in, float4* __restrict__ out,
                             const int* __restrict__ ai, const int* __restrict__ bi,
                             const float4* __restrict__ mix, int Dout) {
    int tid = blockIdx.x * blockDim.x + threadIdx.x;
    if (tid >= Dout * BV) return;
    int j = tid >> 5, lane = tid & 31;
    float4 w = mix[j];
    float4 a = in[(size_t)__ldg(&ai[j]) * BV + lane];
    float4 b = in[(size_t)__ldg(&bi[j]) * BV + lane];
    out[tid] = gate4v(a, b, w.x, w.y, w.z, w.w);
}

// ---------------- logic3 fused with group-sum partials ----------------
__global__ void __launch_bounds__(128) logic3_sum_kernel(
    const float4* __restrict__ in, float4* __restrict__ part,
    const int* __restrict__ ai, const int* __restrict__ bi,
    const float4* __restrict__ mix) {
    __shared__ float4 red[4][32];
    int blk = blockIdx.x;
    int wz = threadIdx.y;
    int lane = threadIdx.x;
    int j0 = blk * 64 + wz * 16;
    float4 acc = f4(0.f);
#pragma unroll
    for (int jj = 0; jj < 16; jj++) {
        int j = j0 + jj;
        float4 w = mix[j];
        float4 a = in[(size_t)__ldg(&ai[j]) * BV + lane];
        float4 b = in[(size_t)__ldg(&bi[j]) * BV + lane];
        float4 g = gate4v(a, b, w.x, w.y, w.z, w.w);
        acc.x += g.x; acc.y += g.y; acc.z += g.z; acc.w += g.w;
    }
    red[wz][lane] = acc;
    __syncthreads();
    if (wz == 0) {
        float4 s = red[0][lane], s1 = red[1][lane], s2 = red[2][lane], s3 = red[3][lane];
        s.x += s1.x + s2.x + s3.x;
        s.y += s1.y + s2.y + s3.y;
        s.z += s1.z + s2.z + s3.z;
        s.w += s1.w + s2.w + s3.w;
        part[(size_t)blk * BV + lane] = s;
    }
}

// ---------------- final reduce ----------------
__global__ void final_sum_kernel(const float* __restrict__ part, float* __restrict__ out) {
    int tid = blockIdx.x * blockDim.x + threadIdx.x;
    if (tid >= 1280) return;
    int cls = tid >> 7, b = tid & 127;
    float s = 0.f;
#pragma unroll
    for (int k = 0; k < 16; k++) s += part[(size_t)(cls * 16 + k) * BB + b];
    out[b * 10 + cls] = s * 0.01f;
}

// ---------------- host launcher ----------------
extern "C" void kernel_launch(void* const* d_in, const int* in_sizes, int n_in,
                              void* d_out, int out_size) {
    const float* x   = (const float*)d_in[0];
    const int*   c1i = (const int*)d_in[1];  const float* c1w = (const float*)d_in[2];
    const int*   c2i = (const int*)d_in[3];  const float* c2w = (const float*)d_in[4];
    const int*   c3i = (const int*)d_in[5];  const float* c3w = (const float*)d_in[6];
    const int*   c4i = (const int*)d_in[7];  const float* c4w = (const float*)d_in[8];
    const int*   l1a = (const int*)d_in[9];  const int* l1b = (const int*)d_in[10];
    const float* l1w = (const float*)d_in[11];
    const int*   l2a = (const int*)d_in[12]; const int* l2b = (const int*)d_in[13];
    const float* l2w = (const float*)d_in[14];
    const int*   l3a = (const int*)d_in[15]; const int* l3b = (const int*)d_in[16];
    const float* l3w = (const float*)d_in[17];

    float *bin, *h1, *h2, *h3, *h4, *g1, *g2, *mixb, *part;
    cudaGetSymbolAddress((void**)&bin,  g_bin);
    cudaGetSymbolAddress((void**)&h1,   g_h1);
    cudaGetSymbolAddress((void**)&h2,   g_h2);
    cudaGetSymbolAddress((void**)&h3,   g_h3);
    cudaGetSymbolAddress((void**)&h4,   g_h4);
    cudaGetSymbolAddress((void**)&g1,   g_g1);
    cudaGetSymbolAddress((void**)&g2,   g_g2);
    cudaGetSymbolAddress((void**)&mixb, g_mix);
    cudaGetSymbolAddress((void**)&part, g_part);

    mix_kernel<<<(N_NODES + 127) / 128, 128>>>(c1w, c2w, c3w, c4w, l1w, l2w, l3w, mixb);
    binarize_kernel<<<dim3(4, 32, 3), dim3(32, 32)>>>(x, bin);

    tree_conv_kernel<32, 4, true> <<<dim3(64, 32),  dim3(64, 4)>>>(bin, (float2*)h1, c1i, mixb + OFF_C1 * 4);
    tree_conv_kernel<16, 4, true> <<<dim3(16, 128), dim3(64, 4)>>>(h1,  (float2*)h2, c2i, mixb + OFF_C2 * 4);
    tree_conv_kernel<8, 4, true>  <<<dim3(4, 512),  dim3(64, 4)>>>(h2,  (float2*)h3, c3i, mixb + OFF_C3 * 4);
    tree_conv_kernel<4, 4, false><<<dim3(1, 1024), dim3(64, 4)>>>(h3,  (float2*)h4, c4i, mixb + OFF_C4 * 4);

    logic_kernel<<<(40960 * BV) / 256, 256>>>((const float4*)h4, (float4*)g1, l1a, l1b, (const float4*)(mixb + OFF_L1 * 4), 40960);
    logic_kernel<<<(20480 * BV) / 256, 256>>>((const float4*)g1, (float4*)g2, l2a, l2b, (const float4*)(mixb + OFF_L2 * 4), 20480);
    logic3_sum_kernel<<<160, dim3(32, 4)>>>((const float4*)g2, (float4*)part, l3a, l3b, (const float4*)(mixb + OFF_L3 * 4));
    final_sum_kernel<<<10, 128>>>(part, (float*)d_out);
}

// round 7
// speedup vs baseline: 1.5706x; 1.5706x over previous
#include <cuda_runtime.h>
#include <cuda_fp16.h>

#define BB 128  // batch
#define BU 32   // batch in uint2 units (4 halves each)

// ---------------- padded geometry, fp16 (halos stay zero: never written) ---
__device__ __align__(16) __half g_bin[9 * 34 * 34 * BB];
__device__ __align__(16) __half g_h1[32 * 18 * 18 * BB];
__device__ __align__(16) __half g_h2[128 * 10 * 10 * BB];
__device__ __align__(16) __half g_h3[512 * 6 * 6 * BB];
__device__ __align__(16) __half g_h4[4096 * BB];
__device__ __align__(16) __half g_g1[40960 * BB];
__device__ __align__(16) __half g_g2[20480 * BB];
__device__ __align__(16) __half2 g_mixh[83552 * 4];  // duplicated-lane coefs
__device__ __align__(16) float g_part[160 * BB];

__constant__ float GC[64] = {
    0, 0, 0, 0,   0, 0, 0, 1,   0, 1, 0, -1,  0, 1, 0, 0,
    0, 0, 1, -1,  0, 0, 1, 0,   0, 1, 1, -2,  0, 1, 1, -1,
    1, -1, -1, 1, 1, -1, -1, 2, 1, 0, -1, 0,  1, 0, -1, 1,
    1, -1, 0, 0,  1, -1, 0, 1,  1, 0, 0, -1,  1, 0, 0, 0};

#define OFF_C1 0
#define OFF_C2 224
#define OFF_C3 1120
#define OFF_C4 4704
#define OFF_L1 11872
#define OFF_L2 52832
#define OFF_L3 73312
#define N_NODES 83552

// ---------------- helpers ----------------
__device__ __forceinline__ __half2 u2h(unsigned int u) {
    __half2 h;
    *reinterpret_cast<unsigned int*>(&h) = u;
    return h;
}
__device__ __forceinline__ unsigned int h2u(__half2 h) {
    return *reinterpret_cast<unsigned int*>(&h);
}
// w0 + w1*a + w2*b + w3*(a*b) on 2 fp16 lanes
__device__ __forceinline__ __half2 gateh(__half2 a, __half2 b,
                                         __half2 w0, __half2 w1, __half2 w2, __half2 w3) {
    return __hfma2(__hmul2(a, b), w3, __hfma2(b, w2, __hfma2(a, w1, w0)));
}

// ---------------- kernel 1: gate mixing -> duplicated half2 coefs ----------
__global__ void mix_kernel(const float* __restrict__ s0, const float* __restrict__ s1,
                           const float* __restrict__ s2, const float* __restrict__ s3,
                           const float* __restrict__ s4, const float* __restrict__ s5,
                           const float* __restrict__ s6, __half2* __restrict__ dst) {
    int tid = blockIdx.x * blockDim.x + threadIdx.x;
    if (tid >= N_NODES) return;
    const int offs[8] = {OFF_C1, OFF_C2, OFF_C3, OFF_C4, OFF_L1, OFF_L2, OFF_L3, N_NODES};
    const float* srcs[7] = {s0, s1, s2, s3, s4, s5, s6};
    int seg = 0;
    while (tid >= offs[seg + 1]) seg++;
    const float* w = srcs[seg] + (size_t)(tid - offs[seg]) * 16;

    float e[16];
    float mx = w[0];
#pragma unroll
    for (int i = 1; i < 16; i++) mx = fmaxf(mx, w[i]);
    float s = 0.f;
#pragma unroll
    for (int i = 0; i < 16; i++) { e[i] = __expf(w[i] - mx); s += e[i]; }
    float inv = 1.f / s;
    float m0 = 0.f, m1 = 0.f, m2 = 0.f, m3 = 0.f;
#pragma unroll
    for (int i = 0; i < 16; i++) {
        float p = e[i] * inv;
        m0 = fmaf(p, GC[i * 4 + 0], m0);
        m1 = fmaf(p, GC[i * 4 + 1], m1);
        m2 = fmaf(p, GC[i * 4 + 2], m2);
        m3 = fmaf(p, GC[i * 4 + 3], m3);
    }
    dst[tid * 4 + 0] = __float2half2_rn(m0);
    dst[tid * 4 + 1] = __float2half2_rn(m1);
    dst[tid * 4 + 2] = __float2half2_rn(m2);
    dst[tid * 4 + 3] = __float2half2_rn(m3);
}

// ---------------- kernel 2: binarize + BCHW -> CHWB fp16 (padded out) ------
__global__ void binarize_kernel(const float* __restrict__ x, __half* __restrict__ bin) {
    __shared__ float tile[32][33];
    int c = blockIdx.z;
    int h = blockIdx.y;
    int bc = blockIdx.x;
    int b = bc * 32 + threadIdx.y;
    tile[threadIdx.y][threadIdx.x] = x[(((size_t)b * 3 + c) * 32 + h) * 32 + threadIdx.x];
    __syncthreads();
    int w = threadIdx.y;
    int bout = bc * 32 + threadIdx.x;
    float v = tile[threadIdx.x][w];
    const float thr[3] = {0.25f, 0.5f, 0.75f};
    const __half one = __float2half(1.f), zero = __float2half(0.f);
#pragma unroll
    for (int t = 0; t < 3; t++) {
        size_t idx = (((size_t)(t * 3 + c)) * 34 * 34 + (size_t)(h + 1) * 34 + (w + 1)) * BB + bout;
        bin[idx] = (v > thr[t]) ? one : zero;
    }
}

// ---------------- tree_conv + or_pool: fp16, 32 uint2-lanes per (o,s) ------
template <int Hin, int SPB, bool PADOUT>
__global__ void __launch_bounds__(32 * SPB, 4) tree_conv_kernel(
    const uint2* __restrict__ in, uint2* __restrict__ out,
    const int* __restrict__ leaf, const __half2* __restrict__ mixh) {
    constexpr int Win = Hin + 2;
    constexpr int Wo = Hin / 2;
    constexpr int Wop = PADOUT ? (Wo + 2) : Wo;
    int o = blockIdx.y;
    __shared__ __half2 smw[28];
    __shared__ int soff[8];
    int t = threadIdx.y * 32 + threadIdx.x;
    if (t < 28) smw[t] = mixh[o * 28 + t];
    if (t < 8) {
        int idx = leaf[o * 8 + t];
        int ch = idx / 9, p = idx % 9;
        soff[t] = (ch * Win * Win + (p / 3) * Win + (p % 3)) * BU;
    }
    __syncthreads();
    int s = blockIdx.x * SPB + threadIdx.y;
    int wo = s % Wo, ho = s / Wo;
    int lane = threadIdx.x;

    __half2 rlo = __float2half2_rn(-60000.f);
    __half2 rhi = rlo;
#pragma unroll
    for (int ph = 0; ph < 2; ph++) {
#pragma unroll
        for (int pw = 0; pw < 2; pw++) {
            int pos = ((2 * ho + ph) * Win + (2 * wo + pw)) * BU + lane;
            uint2 v[8];
#pragma unroll
            for (int l = 0; l < 8; l++) v[l] = in[soff[l] + pos];
            // low half2 (batch 4*lane .. +1)
            __half2 t0 = gateh(u2h(v[0].x), u2h(v[1].x), smw[0], smw[1], smw[2], smw[3]);
            __half2 t1 = gateh(u2h(v[2].x), u2h(v[3].x), smw[4], smw[5], smw[6], smw[7]);
            __half2 t2 = gateh(u2h(v[4].x), u2h(v[5].x), smw[8], smw[9], smw[10], smw[11]);
            __half2 t3 = gateh(u2h(v[6].x), u2h(v[7].x), smw[12], smw[13], smw[14], smw[15]);
            __half2 u0 = gateh(t0, t1, smw[16], smw[17], smw[18], smw[19]);
            __half2 u1 = gateh(t2, t3, smw[20], smw[21], smw[22], smw[23]);
            rlo = __hmax2(rlo, gateh(u0, u1, smw[24], smw[25], smw[26], smw[27]));
            // high half2 (batch 4*lane+2 .. +3)
            t0 = gateh(u2h(v[0].y), u2h(v[1].y), smw[0], smw[1], smw[2], smw[3]);
            t1 = gateh(u2h(v[2].y), u2h(v[3].y), smw[4], smw[5], smw[6], smw[7]);
            t2 = gateh(u2h(v[4].y), u2h(v[5].y), smw[8], smw[9], smw[10], smw[11]);
            t3 = gateh(u2h(v[6].y), u2h(v[7].y), smw[12], smw[13], smw[14], smw[15]);
            u0 = gateh(t0, t1, smw[16], smw[17], smw[18], smw[19]);
            u1 = gateh(t2, t3, smw[20], smw[21], smw[22], smw[23]);
            rhi = __hmax2(rhi, gateh(u0, u1, smw[24], smw[25], smw[26], smw[27]));
        }
    }
    size_t oidx;
    if (PADOUT)
        oidx = ((size_t)o * Wop * Wop + (size_t)(ho + 1) * Wop + (wo + 1)) * BU + lane;
    else
        oidx = ((size_t)o * Wo * Wo + (size_t)ho * Wo + wo) * BU + lane;
    out[oidx] = make_uint2(h2u(rlo), h2u(rhi));
}

// ---------------- logic layers: fp16, uint2 lanes ----------------
__global__ void logic_kernel(const uint2* __restrict__ in, uint2* __restrict__ out,
                             const int* __restrict__ ai, const int* __restrict__ bi,
                             const __half2* __restrict__ mixh, int Dout) {
    int tid = blockIdx.x * blockDim.x + threadIdx.x;
    if (tid >= Dout * BU) return;
    int j = tid >> 5, lane = tid & 31;
    __half2 w0 = mixh[j * 4 + 0], w1 = mixh[j * 4 + 1];
    __half2 w2 = mixh[j * 4 + 2], w3 = mixh[j * 4 + 3];
    uint2 a = in[(size_t)__ldg(&ai[j]) * BU + lane];
    uint2 b = in[(size_t)__ldg(&bi[j]) * BU + lane];
    __half2 rlo = gateh(u2h(a.x), u2h(b.x), w0, w1, w2, w3);
    __half2 rhi = gateh(u2h(a.y), u2h(b.y), w0, w1, w2, w3);
    out[tid] = make_uint2(h2u(rlo), h2u(rhi));
}

// ---------------- logic3 fused with group-sum partials (float accum) -------
__global__ void __launch_bounds__(128) logic3_sum_kernel(
    const uint2* __restrict__ in, float4* __restrict__ part,
    const int* __restrict__ ai, const int* __restrict__ bi,
    const __half2* __restrict__ mixh) {
    __shared__ float4 red[4][32];
    int blk = blockIdx.x;
    int wz = threadIdx.y;
    int lane = threadIdx.x;
    int j0 = blk * 64 + wz * 16;
    float4 acc = make_float4(0.f, 0.f, 0.f, 0.f);
#pragma unroll
    for (int jj = 0; jj < 16; jj++) {
        int j = j0 + jj;
        __half2 w0 = mixh[j * 4 + 0], w1 = mixh[j * 4 + 1];
        __half2 w2 = mixh[j * 4 + 2], w3 = mixh[j * 4 + 3];
        uint2 a = in[(size_t)__ldg(&ai[j]) * BU + lane];
        uint2 b = in[(size_t)__ldg(&bi[j]) * BU + lane];
        float2 glo = __half22float2(gateh(u2h(a.x), u2h(b.x), w0, w1, w2, w3));
        float2 ghi = __half22float2(gateh(u2h(a.y), u2h(b.y), w0, w1, w2, w3));
        acc.x += glo.x; acc.y += glo.y; acc.z += ghi.x; acc.w += ghi.y;
    }
    red[wz][lane] = acc;
    __syncthreads();
    if (wz == 0) {
        float4 s = red[0][lane], s1 = red[1][lane], s2 = red[2][lane], s3 = red[3][lane];
        s.x += s1.x + s2.x + s3.x;
        s.y += s1.y + s2.y + s3.y;
        s.z += s1.z + s2.z + s3.z;
        s.w += s1.w + s2.w + s3.w;
        part[(size_t)blk * BU + lane] = s;
    }
}

// ---------------- final reduce ----------------
__global__ void final_sum_kernel(const float* __restrict__ part, float* __restrict__ out) {
    int tid = blockIdx.x * blockDim.x + threadIdx.x;
    if (tid >= 1280) return;
    int cls = tid >> 7, b = tid & 127;
    float s = 0.f;
#pragma unroll
    for (int k = 0; k < 16; k++) s += part[(size_t)(cls * 16 + k) * BB + b];
    out[b * 10 + cls] = s * 0.01f;
}

// ---------------- host launcher ----------------
extern "C" void kernel_launch(void* const* d_in, const int* in_sizes, int n_in,
                              void* d_out, int out_size) {
    const float* x   = (const float*)d_in[0];
    const int*   c1i = (const int*)d_in[1];  const float* c1w = (const float*)d_in[2];
    const int*   c2i = (const int*)d_in[3];  const float* c2w = (const float*)d_in[4];
    const int*   c3i = (const int*)d_in[5];  const float* c3w = (const float*)d_in[6];
    const int*   c4i = (const int*)d_in[7];  const float* c4w = (const float*)d_in[8];
    const int*   l1a = (const int*)d_in[9];  const int* l1b = (const int*)d_in[10];
    const float* l1w = (const float*)d_in[11];
    const int*   l2a = (const int*)d_in[12]; const int* l2b = (const int*)d_in[13];
    const float* l2w = (const float*)d_in[14];
    const int*   l3a = (const int*)d_in[15]; const int* l3b = (const int*)d_in[16];
    const float* l3w = (const float*)d_in[17];

    __half *bin, *h1, *h2, *h3, *h4, *g1, *g2;
    __half2* mixh;
    float* part;
    cudaGetSymbolAddress((void**)&bin,  g_bin);
    cudaGetSymbolAddress((void**)&h1,   g_h1);
    cudaGetSymbolAddress((void**)&h2,   g_h2);
    cudaGetSymbolAddress((void**)&h3,   g_h3);
    cudaGetSymbolAddress((void**)&h4,   g_h4);
    cudaGetSymbolAddress((void**)&g1,   g_g1);
    cudaGetSymbolAddress((void**)&g2,   g_g2);
    cudaGetSymbolAddress((void**)&mixh, g_mixh);
    cudaGetSymbolAddress((void**)&part, g_part);

    mix_kernel<<<(N_NODES + 127) / 128, 128>>>(c1w, c2w, c3w, c4w, l1w, l2w, l3w, mixh);
    binarize_kernel<<<dim3(4, 32, 3), dim3(32, 32)>>>(x, bin);

    tree_conv_kernel<32, 8, true> <<<dim3(32, 32),  dim3(32, 8)>>>((const uint2*)bin, (uint2*)h1, c1i, mixh + OFF_C1 * 4);
    tree_conv_kernel<16, 8, true> <<<dim3(8, 128),  dim3(32, 8)>>>((const uint2*)h1,  (uint2*)h2, c2i, mixh + OFF_C2 * 4);
    tree_conv_kernel<8, 8, true>  <<<dim3(2, 512),  dim3(32, 8)>>>((const uint2*)h2,  (uint2*)h3, c3i, mixh + OFF_C3 * 4);
    tree_conv_kernel<4, 4, false><<<dim3(1, 1024), dim3(32, 4)>>>((const uint2*)h3,  (uint2*)h4, c4i, mixh + OFF_C4 * 4);

    logic_kernel<<<(40960 * BU) / 256, 256>>>((const uint2*)h4, (uint2*)g1, l1a, l1b, mixh + OFF_L1 * 4, 40960);
    logic_kernel<<<(20480 * BU) / 256, 256>>>((const uint2*)g1, (uint2*)g2, l2a, l2b, mixh + OFF_L2 * 4, 20480);
    logic3_sum_kernel<<<160, dim3(32, 4)>>>((const uint2*)g2, (float4*)part, l3a, l3b, mixh + OFF_L3 * 4);
    final_sum_kernel<<<10, 128>>>(part, (float*)d_out);
}